// round 15
// baseline (speedup 1.0000x reference)
#include <cuda_runtime.h>
#include <cuda_bf16.h>
#include <cstdint>
#include <math.h>

#define NN 8192
#define DD 128
#define NE (NN*3)

// ---------------- device scratch (no allocations allowed) ----------------
__device__ float g_sq[NN];
__device__ __nv_bfloat16 g_xbf[(size_t)NN*DD];
__device__ unsigned long long g_cand[2ull*NN*32];   // [split][row][32] approx top keys
__device__ int g_nbr[NE];
__device__ float g_xp[(size_t)NN*256];    // x @ W, [N][H=2][128]
__device__ float g_as[NN*2];
__device__ float g_ad[NN*2];
__device__ float g_denom[NN*2];
__device__ float g_acc[(size_t)NN*256];   // unnormalized messages [N][H][128]

__device__ __forceinline__ unsigned encf(float f){
  unsigned u = __float_as_uint(f);
  return (u & 0x80000000u) ? ~u : (u | 0x80000000u);
}
__device__ __forceinline__ float decf(unsigned u){
  return (u & 0x80000000u) ? __uint_as_float(u ^ 0x80000000u) : __uint_as_float(~u);
}
__device__ __forceinline__ void ins3(unsigned long long k,
                                     unsigned long long &b0,
                                     unsigned long long &b1,
                                     unsigned long long &b2){
  if (k < b2){
    if (k < b1){
      b2 = b1;
      if (k < b0){ b1 = b0; b0 = k; } else { b1 = k; }
    } else { b2 = k; }
  }
}
// caller pre-guards with key < b[3]
__device__ __forceinline__ void ins4(unsigned long long k, unsigned long long* b){
  b[3] = k;
  #pragma unroll
  for (int s = 3; s > 0; s--){
    if (b[s] < b[s-1]){ unsigned long long t = b[s]; b[s] = b[s-1]; b[s-1] = t; }
  }
}

__device__ __forceinline__ uint32_t smem_u32(const void* p){
  uint32_t a;
  asm("{ .reg .u64 t; cvta.to.shared.u64 t, %1; cvt.u32.u64 %0, t; }" : "=r"(a) : "l"(p));
  return a;
}
__device__ __forceinline__ void ldsm4(uint32_t &r0, uint32_t &r1, uint32_t &r2, uint32_t &r3, uint32_t a){
  asm volatile("ldmatrix.sync.aligned.m8n8.x4.shared.b16 {%0,%1,%2,%3}, [%4];"
    : "=r"(r0), "=r"(r1), "=r"(r2), "=r"(r3) : "r"(a));
}
__device__ __forceinline__ void mma16816(float* d, const uint32_t* a, uint32_t b0, uint32_t b1){
  asm volatile("mma.sync.aligned.m16n8k16.row.col.f32.bf16.bf16.f32 "
    "{%0,%1,%2,%3}, {%4,%5,%6,%7}, {%8,%9}, {%0,%1,%2,%3};"
    : "+f"(d[0]), "+f"(d[1]), "+f"(d[2]), "+f"(d[3])
    : "r"(a[0]), "r"(a[1]), "r"(a[2]), "r"(a[3]), "r"(b0), "r"(b1));
}
// cp.async (LDGSTS) helpers — sm_80+ family-safe
__device__ __forceinline__ void cp_async16(uint32_t s, const void* g){
  asm volatile("cp.async.cg.shared.global [%0], [%1], 16;" :: "r"(s), "l"(g));
}
__device__ __forceinline__ void cp_async4(uint32_t s, const void* g){
  asm volatile("cp.async.ca.shared.global [%0], [%1], 4;" :: "r"(s), "l"(g));
}
__device__ __forceinline__ void cp_commit(){ asm volatile("cp.async.commit_group;" ::: "memory"); }
__device__ __forceinline__ void cp_wait0(){ asm volatile("cp.async.wait_group 0;" ::: "memory"); }

// ---------------- k_prep: fused row squared norm + bf16 convert (warp per row) ----
__global__ void k_prep(const float4* __restrict__ X4){
  int g = blockIdx.x*blockDim.x + threadIdx.x;
  int row = g >> 5, lane = g & 31;
  if (row >= NN) return;
  float4 v = X4[row*32 + lane];
  __nv_bfloat162 p0, p1;
  p0.x = __float2bfloat16(v.x); p0.y = __float2bfloat16(v.y);
  p1.x = __float2bfloat16(v.z); p1.y = __float2bfloat16(v.w);
  ((__nv_bfloat162*)g_xbf)[(size_t)row*64 + lane*2]     = p0;
  ((__nv_bfloat162*)g_xbf)[(size_t)row*64 + lane*2 + 1] = p1;
  float s = v.x*v.x + v.y*v.y + v.z*v.z + v.w*v.w;
  #pragma unroll
  for (int o = 16; o; o >>= 1) s += __shfl_xor_sync(0xffffffffu, s, o);
  if (lane == 0) g_sq[row] = s;
}

// ---------------- k_xp v2: full-K smem, float4 LDS (grid 256 = 128 ib x 2 heads) ---
static constexpr int XP_SMEM = (128*64 + 128*128) * 4;
__global__ __launch_bounds__(256) void k_xp(const float* __restrict__ X,
                                            const float* __restrict__ W){
  extern __shared__ float xsm[];
  float* sA = xsm;
  float* sW = xsm + 128*64;
  const float4* X4 = (const float4*)X;
  const float4* W4 = (const float4*)W;
  int tid = threadIdx.x;
  int tx = tid & 15, ty = tid >> 4;
  int ib = blockIdx.x >> 1, h = blockIdx.x & 1;
  int i0 = ib*64;

  #pragma unroll
  for (int l = 0; l < 8; l++){
    int idx = tid + l*256;
    int r = idx & 63, kc = idx >> 6;
    float4 v = X4[(size_t)(i0 + r)*32 + kc];
    sA[(kc*4+0)*64 + r] = v.x;
    sA[(kc*4+1)*64 + r] = v.y;
    sA[(kc*4+2)*64 + r] = v.z;
    sA[(kc*4+3)*64 + r] = v.w;
  }
  #pragma unroll
  for (int l = 0; l < 16; l++){
    int idx = tid + l*256;
    int k = idx >> 5, c4 = idx & 31;
    ((float4*)sW)[k*32 + c4] = W4[(size_t)k*64 + h*32 + c4];
  }
  __syncthreads();

  float acc[4][8];
  #pragma unroll
  for (int a = 0; a < 4; a++)
    #pragma unroll
    for (int b = 0; b < 8; b++) acc[a][b] = 0.f;

  #pragma unroll 4
  for (int k = 0; k < 128; k++){
    float4 a4 = *(const float4*)(sA + k*64 + 4*ty);
    float4 b0 = *(const float4*)(sW + k*128 + 4*tx);
    float4 b1 = *(const float4*)(sW + k*128 + 64 + 4*tx);
    float a[4] = {a4.x, a4.y, a4.z, a4.w};
    float b[8] = {b0.x, b0.y, b0.z, b0.w, b1.x, b1.y, b1.z, b1.w};
    #pragma unroll
    for (int mi = 0; mi < 4; mi++)
      #pragma unroll
      for (int mj = 0; mj < 8; mj++)
        acc[mi][mj] = fmaf(a[mi], b[mj], acc[mi][mj]);
  }

  #pragma unroll
  for (int mi = 0; mi < 4; mi++){
    size_t base = (size_t)(i0 + 4*ty + mi)*256 + h*128;
    *(float4*)(g_xp + base + 4*tx)      = make_float4(acc[mi][0], acc[mi][1], acc[mi][2], acc[mi][3]);
    *(float4*)(g_xp + base + 64 + 4*tx) = make_float4(acc[mi][4], acc[mi][5], acc[mi][6], acc[mi][7]);
  }
}

// ---------------- k_attn: attention coeffs + init denom/acc ----------------
__global__ void k_attn(const float* __restrict__ att_src,
                       const float* __restrict__ att_dst){
  int g = blockIdx.x*blockDim.x + threadIdx.x;
  int n = g >> 5, lane = g & 31;
  if (n >= NN) return;
  const float4* xp4 = (const float4*)g_xp;
  float4 x0 = xp4[(size_t)n*64 + lane];
  float4 x1 = xp4[(size_t)n*64 + 32 + lane];
  const float4* s4 = (const float4*)att_src;
  const float4* d4 = (const float4*)att_dst;
  float4 a0 = s4[lane], a1 = s4[32 + lane];
  float4 c0 = d4[lane], c1 = d4[32 + lane];
  float vs0 = x0.x*a0.x + x0.y*a0.y + x0.z*a0.z + x0.w*a0.w;
  float vs1 = x1.x*a1.x + x1.y*a1.y + x1.z*a1.z + x1.w*a1.w;
  float vd0 = x0.x*c0.x + x0.y*c0.y + x0.z*c0.z + x0.w*c0.w;
  float vd1 = x1.x*c1.x + x1.y*c1.y + x1.z*c1.z + x1.w*c1.w;
  #pragma unroll
  for (int o = 16; o; o >>= 1){
    vs0 += __shfl_xor_sync(0xffffffffu, vs0, o);
    vs1 += __shfl_xor_sync(0xffffffffu, vs1, o);
    vd0 += __shfl_xor_sync(0xffffffffu, vd0, o);
    vd1 += __shfl_xor_sync(0xffffffffu, vd1, o);
  }
  if (lane == 0){
    g_as[n*2+0] = vs0; g_as[n*2+1] = vs1;
    g_ad[n*2+0] = vd0; g_ad[n*2+1] = vd1;
    g_denom[n*2+0] = 0.f; g_denom[n*2+1] = 0.f;
  }
  float4 z = make_float4(0.f, 0.f, 0.f, 0.f);
  ((float4*)g_acc)[(size_t)n*64 + lane] = z;
  ((float4*)g_acc)[(size_t)n*64 + 32 + lane] = z;
}

// ---------------- k_filter v5: 512 thr, cp.async, branchless min-gated epilogue ---
static constexpr int PITCH  = 272;
static constexpr int SM_A   = 0;
static constexpr int SM_B0  = 34816;
static constexpr int SM_B1  = 69632;
static constexpr int SM_SQ0 = 104448;
static constexpr int SM_SQ1 = 104960;
static constexpr int SM_TOT = 105472;
static constexpr int ROW_BYTES  = 256;            // 128 bf16 per row
static constexpr int TILE_BYTES = 128*ROW_BYTES;  // 32768 per 128-row tile

__global__ __launch_bounds__(512, 1) void k_filter(){
  extern __shared__ char smem[];
  uint32_t sbase = smem_u32(smem);
  int tid = threadIdx.x;
  int wid = tid >> 5, lane = tid & 31;
  int wr = wid & 7, wc = wid >> 3;
  int ib = blockIdx.x >> 1, split = blockIdx.x & 1;
  int i0 = ib*128;

  // per-thread B-copy slots (constant across tiles)
  uint32_t bOff[4];
  const char* gB[4];
  #pragma unroll
  for (int l = 0; l < 4; l++){
    int idx = tid + l*512;
    int r = idx >> 4, c = idx & 15;
    bOff[l] = (uint32_t)(r*PITCH + c*16);
    gB[l] = (const char*)g_xbf + (size_t)(split*4096 + r)*ROW_BYTES + c*16;
  }

  // prologue: cp.async B tile 0 + sq0; A tile via normal loads
  #pragma unroll
  for (int l = 0; l < 4; l++) cp_async16(sbase + SM_B0 + bOff[l], gB[l]);
  if (tid < 128) cp_async4(sbase + SM_SQ0 + tid*4, g_sq + split*4096 + tid);
  cp_commit();

  #pragma unroll
  for (int l = 0; l < 4; l++){
    int idx = tid + l*512;
    int r = idx >> 4, c = idx & 15;
    uint4 v = ((const uint4*)(g_xbf + (size_t)(i0 + r)*128))[c];
    *(uint4*)(smem + SM_A + r*PITCH + c*16) = v;
  }
  cp_wait0();
  __syncthreads();

  uint32_t aAddr = sbase + SM_A
                 + (uint32_t)(16*wr + (lane & 7) + 8*((lane >> 3) & 1))*PITCH
                 + (uint32_t)(((lane >> 4) & 1) << 4);
  uint32_t bRowOff = (uint32_t)(64*wc + (lane & 7) + 8*((lane >> 4) & 1))*PITCH
                   + (uint32_t)(((lane >> 3) & 1) << 4);

  unsigned long long bu[4], bl[4];
  #pragma unroll
  for (int s = 0; s < 4; s++){ bu[s] = ~0ull; bl[s] = ~0ull; }
  float thrU = 1e30f, thrL = 1e30f;

  int q = lane & 3;
  int rsub = lane >> 2;
  int cBase = 64*wc + 2*q;   // t-invariant column base for this thread

  for (int t = 0; t < 32; t++){
    int j0 = split*4096 + t*128;
    uint32_t bBase = sbase + ((t & 1) ? SM_B1 : SM_B0);
    const float* sq = (const float*)(smem + ((t & 1) ? SM_SQ1 : SM_SQ0));

    // prefetch next tile (overlaps with mma + epilogue)
    if (t < 31){
      uint32_t nb = sbase + (((t + 1) & 1) ? SM_B1 : SM_B0);
      size_t goff = (size_t)(t + 1)*TILE_BYTES;
      #pragma unroll
      for (int l = 0; l < 4; l++) cp_async16(nb + bOff[l], gB[l] + goff);
      if (tid < 128)
        cp_async4(sbase + (((t + 1) & 1) ? SM_SQ1 : SM_SQ0) + tid*4,
                  g_sq + split*4096 + (t + 1)*128 + tid);
      cp_commit();
    }

    float acc[8][4];
    #pragma unroll
    for (int a = 0; a < 8; a++)
      #pragma unroll
      for (int b = 0; b < 4; b++) acc[a][b] = 0.f;

    #pragma unroll
    for (int ks = 0; ks < 8; ks++){
      uint32_t A[4];
      ldsm4(A[0], A[1], A[2], A[3], aAddr + ks*32);
      #pragma unroll
      for (int p = 0; p < 4; p++){
        uint32_t b0, b1, b2, b3;
        ldsm4(b0, b1, b2, b3, bBase + bRowOff + (uint32_t)(p*16)*PITCH + ks*32);
        mma16816(acc[2*p],   A, b0, b1);
        mma16816(acc[2*p+1], A, b2, b3);
      }
    }

    // epilogue: convert acc -> d2 in place; min-gate the (rare) insert pass
    #pragma unroll
    for (int tt = 0; tt < 8; tt++){
      int c0 = cBase + 16*(tt >> 1) + 8*(tt & 1);
      float sq0 = sq[c0], sq1 = sq[c0 + 1];
      acc[tt][0] = fmaf(-2.0f, acc[tt][0], sq0);
      acc[tt][1] = fmaf(-2.0f, acc[tt][1], sq1);
      acc[tt][2] = fmaf(-2.0f, acc[tt][2], sq0);
      acc[tt][3] = fmaf(-2.0f, acc[tt][3], sq1);
    }
    float mU = acc[0][0], mL = acc[0][2];
    #pragma unroll
    for (int tt = 0; tt < 8; tt++){
      mU = fminf(mU, fminf(acc[tt][0], acc[tt][1]));
      mL = fminf(mL, fminf(acc[tt][2], acc[tt][3]));
    }
    if (mU < thrU){
      #pragma unroll
      for (int tt = 0; tt < 8; tt++){
        int c0 = j0 + cBase + 16*(tt >> 1) + 8*(tt & 1);
        if (acc[tt][0] < thrU){
          ins4(((unsigned long long)encf(acc[tt][0]) << 32) | (unsigned)c0, bu);
          thrU = fminf(decf((unsigned)(bu[3] >> 32)), 1e30f);
        }
        if (acc[tt][1] < thrU){
          ins4(((unsigned long long)encf(acc[tt][1]) << 32) | (unsigned)(c0 + 1), bu);
          thrU = fminf(decf((unsigned)(bu[3] >> 32)), 1e30f);
        }
      }
    }
    if (mL < thrL){
      #pragma unroll
      for (int tt = 0; tt < 8; tt++){
        int c0 = j0 + cBase + 16*(tt >> 1) + 8*(tt & 1);
        if (acc[tt][2] < thrL){
          ins4(((unsigned long long)encf(acc[tt][2]) << 32) | (unsigned)c0, bl);
          thrL = fminf(decf((unsigned)(bl[3] >> 32)), 1e30f);
        }
        if (acc[tt][3] < thrL){
          ins4(((unsigned long long)encf(acc[tt][3]) << 32) | (unsigned)(c0 + 1), bl);
          thrL = fminf(decf((unsigned)(bl[3] >> 32)), 1e30f);
        }
      }
    }

    if (t < 31) cp_wait0();
    __syncthreads();
  }

  // write per-(row, wc, q) top-4: rows 16wr + rsub and +8; 8 buckets/row/split
  int rowU = i0 + 16*wr + rsub;
  int rowL = rowU + 8;
  size_t baseU = ((size_t)split*NN + rowU)*32 + wc*16 + q*4;
  size_t baseL = ((size_t)split*NN + rowL)*32 + wc*16 + q*4;
  #pragma unroll
  for (int s = 0; s < 4; s++){
    g_cand[baseU + s] = bu[s];
    g_cand[baseL + s] = bl[s];
  }
}

// ---------------- k_rescore: exact fp32, warp per row, 64 candidates --------------
__global__ __launch_bounds__(256) void k_rescore(const float* __restrict__ X){
  int g = blockIdx.x*blockDim.x + threadIdx.x;
  int row = g >> 5, lane = g & 31;
  if (row >= NN) return;
  const float4* __restrict__ X4 = (const float4*)X;
  float4 xi = X4[(size_t)row*32 + lane];
  unsigned long long k0 = g_cand[(size_t)row*32 + lane];            // split 0
  unsigned long long k1 = g_cand[((size_t)NN + row)*32 + lane];     // split 1
  int jl0 = (int)(k0 & 0xffffffffull) & (NN - 1);
  int jl1 = (int)(k1 & 0xffffffffull) & (NN - 1);
  float sqi = g_sq[row];
  unsigned long long b0 = ~0ull, b1 = ~0ull, b2 = ~0ull;
  #pragma unroll 4
  for (int c = 0; c < 32; c++){
    int ja = __shfl_sync(0xffffffffu, jl0, c);
    int jb = __shfl_sync(0xffffffffu, jl1, c);
    float4 xa = X4[(size_t)ja*32 + lane];
    float4 xb = X4[(size_t)jb*32 + lane];
    float pa = xi.x*xa.x + xi.y*xa.y + xi.z*xa.z + xi.w*xa.w;
    float pb = xi.x*xb.x + xi.y*xb.y + xi.z*xb.z + xi.w*xb.w;
    #pragma unroll
    for (int o = 16; o; o >>= 1){
      pa += __shfl_xor_sync(0xffffffffu, pa, o);
      pb += __shfl_xor_sync(0xffffffffu, pb, o);
    }
    float d2a = (sqi + g_sq[ja]) - 2.0f*pa;
    float d2b = (sqi + g_sq[jb]) - 2.0f*pb;
    ins3(((unsigned long long)encf(d2a) << 32) | (unsigned)ja, b0, b1, b2);
    ins3(((unsigned long long)encf(d2b) << 32) | (unsigned)jb, b0, b1, b2);
  }
  if (lane == 0){
    g_nbr[row*3+0] = (int)(b0 & 0xffffffffull);
    g_nbr[row*3+1] = (int)(b1 & 0xffffffffull);
    g_nbr[row*3+2] = (int)(b2 & 0xffffffffull);
  }
}

// ---------------- k_edge: fused softmax-weight + aggregate (warp per edge-head) ----
__global__ void k_edge(){
  int g = blockIdx.x*blockDim.x + threadIdx.x;
  int eh = g >> 5, lane = g & 31;
  if (eh >= NE*2) return;
  int e = eh >> 1, h = eh & 1;
  int s = e/3;
  int d = g_nbr[e];
  float v = g_as[s*2+h] + g_ad[d*2+h];
  v = v > 0.f ? v : 0.2f*v;
  float w = __expf(v);
  if (lane == 0) atomicAdd(&g_denom[d*2+h], w);
  const float4* xp4 = (const float4*)g_xp;
  float4 xv = xp4[(size_t)s*64 + h*32 + lane];
  float* dst = &g_acc[(size_t)d*256 + h*128 + lane*4];
  atomicAdd(dst+0, w*xv.x);
  atomicAdd(dst+1, w*xv.y);
  atomicAdd(dst+2, w*xv.z);
  atomicAdd(dst+3, w*xv.w);
}

// ---------------- k_final: normalize + head-mean + bias + LN + ReLU + residual -----
__global__ void k_final(const float* __restrict__ X,
                        const float* __restrict__ bias,
                        const float* __restrict__ gamma,
                        const float* __restrict__ beta,
                        float* __restrict__ out){
  int g = blockIdx.x*blockDim.x + threadIdx.x;
  int n = g >> 5, lane = g & 31;
  if (n >= NN) return;
  float inv0 = 1.0f / g_denom[n*2+0];
  float inv1 = 1.0f / g_denom[n*2+1];
  float v[4];
  #pragma unroll
  for (int c = 0; c < 4; c++){
    int dd = lane*4 + c;
    float a0 = g_acc[(size_t)n*256 + dd] * inv0;
    float a1 = g_acc[(size_t)n*256 + 128 + dd] * inv1;
    v[c] = 0.5f*(a0 + a1) + bias[dd];
  }
  float s = v[0]+v[1]+v[2]+v[3];
  #pragma unroll
  for (int o = 16; o; o >>= 1) s += __shfl_xor_sync(0xffffffffu, s, o);
  float mu = s * (1.0f/128.0f);
  float q = 0.f;
  #pragma unroll
  for (int c = 0; c < 4; c++){ float t = v[c]-mu; q += t*t; }
  #pragma unroll
  for (int o = 16; o; o >>= 1) q += __shfl_xor_sync(0xffffffffu, q, o);
  float rstd = rsqrtf(q*(1.0f/128.0f) + 1e-5f);
  #pragma unroll
  for (int c = 0; c < 4; c++){
    int dd = lane*4 + c;
    float y = (v[c]-mu)*rstd*gamma[dd] + beta[dd];
    y = y > 0.f ? y : 0.f;
    out[(size_t)n*128 + dd] = X[(size_t)n*128 + dd] + y;
  }
}

// ---------------- launch ----------------
extern "C" void kernel_launch(void* const* d_in, const int* in_sizes, int n_in,
                              void* d_out, int out_size) {
  const float* prototypes = (const float*)d_in[0];
  // d_in[1] = labels (unused in forward)
  const float* W       = (const float*)d_in[2];
  const float* att_src = (const float*)d_in[3];
  const float* att_dst = (const float*)d_in[4];
  const float* bias    = (const float*)d_in[5];
  const float* gamma   = (const float*)d_in[6];
  const float* beta    = (const float*)d_in[7];
  float* out = (float*)d_out;

  cudaFuncSetAttribute(k_filter, cudaFuncAttributeMaxDynamicSharedMemorySize, SM_TOT);
  cudaFuncSetAttribute(k_xp, cudaFuncAttributeMaxDynamicSharedMemorySize, XP_SMEM);

  // order: k_filter at launch index 3 (the ncu-profiled slot)
  k_prep<<<NN/8, 256>>>((const float4*)prototypes);
  k_xp<<<256, 256, XP_SMEM>>>(prototypes, W);
  k_attn<<<NN/8, 256>>>(att_src, att_dst);
  k_filter<<<128, 512, SM_TOT>>>();
  k_rescore<<<NN/8, 256>>>(prototypes);
  k_edge<<<(NE*2*32+255)/256, 256>>>();
  k_final<<<NN/8, 256>>>(prototypes, bias, gamma, beta, out);
}

// round 16
// speedup vs baseline: 1.0491x; 1.0491x over previous
#include <cuda_runtime.h>
#include <cuda_bf16.h>
#include <cstdint>
#include <math.h>

#define NN 8192
#define DD 128
#define NE (NN*3)

// ---------------- device scratch (no allocations allowed) ----------------
__device__ float g_sq[NN];
__device__ __nv_bfloat16 g_xbf[(size_t)NN*DD];
__device__ unsigned long long g_cand[2ull*NN*32];   // [split][row][32] approx top keys
__device__ int g_nbr[NE];
__device__ float g_xp[(size_t)NN*256];    // x @ W, [N][H=2][128]
__device__ float g_as[NN*2];
__device__ float g_ad[NN*2];
__device__ float g_denom[NN*2];
__device__ float g_acc[(size_t)NN*256];   // unnormalized messages [N][H][128]

__device__ __forceinline__ unsigned encf(float f){
  unsigned u = __float_as_uint(f);
  return (u & 0x80000000u) ? ~u : (u | 0x80000000u);
}
__device__ __forceinline__ float decf(unsigned u){
  return (u & 0x80000000u) ? __uint_as_float(u ^ 0x80000000u) : __uint_as_float(~u);
}
__device__ __forceinline__ void ins3(unsigned long long k,
                                     unsigned long long &b0,
                                     unsigned long long &b1,
                                     unsigned long long &b2){
  if (k < b2){
    if (k < b1){
      b2 = b1;
      if (k < b0){ b1 = b0; b0 = k; } else { b1 = k; }
    } else { b2 = k; }
  }
}
// caller pre-guards with key < b[3]
__device__ __forceinline__ void ins4(unsigned long long k, unsigned long long* b){
  b[3] = k;
  #pragma unroll
  for (int s = 3; s > 0; s--){
    if (b[s] < b[s-1]){ unsigned long long t = b[s]; b[s] = b[s-1]; b[s-1] = t; }
  }
}

__device__ __forceinline__ uint32_t smem_u32(const void* p){
  uint32_t a;
  asm("{ .reg .u64 t; cvta.to.shared.u64 t, %1; cvt.u32.u64 %0, t; }" : "=r"(a) : "l"(p));
  return a;
}
__device__ __forceinline__ void ldsm4(uint32_t &r0, uint32_t &r1, uint32_t &r2, uint32_t &r3, uint32_t a){
  asm volatile("ldmatrix.sync.aligned.m8n8.x4.shared.b16 {%0,%1,%2,%3}, [%4];"
    : "=r"(r0), "=r"(r1), "=r"(r2), "=r"(r3) : "r"(a));
}
__device__ __forceinline__ void mma16816(float* d, const uint32_t* a, uint32_t b0, uint32_t b1){
  asm volatile("mma.sync.aligned.m16n8k16.row.col.f32.bf16.bf16.f32 "
    "{%0,%1,%2,%3}, {%4,%5,%6,%7}, {%8,%9}, {%0,%1,%2,%3};"
    : "+f"(d[0]), "+f"(d[1]), "+f"(d[2]), "+f"(d[3])
    : "r"(a[0]), "r"(a[1]), "r"(a[2]), "r"(a[3]), "r"(b0), "r"(b1));
}

// ---------------- k_prep: fused row squared norm + bf16 convert (warp per row) ----
__global__ void k_prep(const float4* __restrict__ X4){
  int g = blockIdx.x*blockDim.x + threadIdx.x;
  int row = g >> 5, lane = g & 31;
  if (row >= NN) return;
  float4 v = X4[row*32 + lane];
  __nv_bfloat162 p0, p1;
  p0.x = __float2bfloat16(v.x); p0.y = __float2bfloat16(v.y);
  p1.x = __float2bfloat16(v.z); p1.y = __float2bfloat16(v.w);
  ((__nv_bfloat162*)g_xbf)[(size_t)row*64 + lane*2]     = p0;
  ((__nv_bfloat162*)g_xbf)[(size_t)row*64 + lane*2 + 1] = p1;
  float s = v.x*v.x + v.y*v.y + v.z*v.z + v.w*v.w;
  #pragma unroll
  for (int o = 16; o; o >>= 1) s += __shfl_xor_sync(0xffffffffu, s, o);
  if (lane == 0) g_sq[row] = s;
}

// ---------------- k_xp v3: full-K smem + fused attention coefficients -------------
// grid 256 = 128 i-tiles(64 rows) x 2 heads. After GEMM, reduce a_s/a_d in-register.
static constexpr int XP_SMEM = (128*64 + 128*128) * 4;
__global__ __launch_bounds__(256) void k_xp(const float* __restrict__ X,
                                            const float* __restrict__ W,
                                            const float* __restrict__ att_src,
                                            const float* __restrict__ att_dst){
  extern __shared__ float xsm[];
  float* sA = xsm;
  float* sW = xsm + 128*64;
  const float4* X4 = (const float4*)X;
  const float4* W4 = (const float4*)W;
  int tid = threadIdx.x;
  int tx = tid & 15, ty = tid >> 4;
  int ib = blockIdx.x >> 1, h = blockIdx.x & 1;
  int i0 = ib*64;

  #pragma unroll
  for (int l = 0; l < 8; l++){
    int idx = tid + l*256;
    int r = idx & 63, kc = idx >> 6;
    float4 v = X4[(size_t)(i0 + r)*32 + kc];
    sA[(kc*4+0)*64 + r] = v.x;
    sA[(kc*4+1)*64 + r] = v.y;
    sA[(kc*4+2)*64 + r] = v.z;
    sA[(kc*4+3)*64 + r] = v.w;
  }
  #pragma unroll
  for (int l = 0; l < 16; l++){
    int idx = tid + l*256;
    int k = idx >> 5, c4 = idx & 31;
    ((float4*)sW)[k*32 + c4] = W4[(size_t)k*64 + h*32 + c4];
  }
  __syncthreads();

  float acc[4][8];
  #pragma unroll
  for (int a = 0; a < 4; a++)
    #pragma unroll
    for (int b = 0; b < 8; b++) acc[a][b] = 0.f;

  #pragma unroll 4
  for (int k = 0; k < 128; k++){
    float4 a4 = *(const float4*)(sA + k*64 + 4*ty);
    float4 b0 = *(const float4*)(sW + k*128 + 4*tx);
    float4 b1 = *(const float4*)(sW + k*128 + 64 + 4*tx);
    float a[4] = {a4.x, a4.y, a4.z, a4.w};
    float b[8] = {b0.x, b0.y, b0.z, b0.w, b1.x, b1.y, b1.z, b1.w};
    #pragma unroll
    for (int mi = 0; mi < 4; mi++)
      #pragma unroll
      for (int mj = 0; mj < 8; mj++)
        acc[mi][mj] = fmaf(a[mi], b[mj], acc[mi][mj]);
  }

  #pragma unroll
  for (int mi = 0; mi < 4; mi++){
    size_t base = (size_t)(i0 + 4*ty + mi)*256 + h*128;
    *(float4*)(g_xp + base + 4*tx)      = make_float4(acc[mi][0], acc[mi][1], acc[mi][2], acc[mi][3]);
    *(float4*)(g_xp + base + 64 + 4*tx) = make_float4(acc[mi][4], acc[mi][5], acc[mi][6], acc[mi][7]);
  }

  // fused attention coefficients: a_s/a_d for rows 4ty..4ty+3, head h
  float4 s0 = ((const float4*)att_src)[h*32 + tx];
  float4 s1 = ((const float4*)att_src)[h*32 + 16 + tx];
  float4 d0 = ((const float4*)att_dst)[h*32 + tx];
  float4 d1 = ((const float4*)att_dst)[h*32 + 16 + tx];
  float ps[4], pd[4];
  #pragma unroll
  for (int mi = 0; mi < 4; mi++){
    ps[mi] = acc[mi][0]*s0.x + acc[mi][1]*s0.y + acc[mi][2]*s0.z + acc[mi][3]*s0.w
           + acc[mi][4]*s1.x + acc[mi][5]*s1.y + acc[mi][6]*s1.z + acc[mi][7]*s1.w;
    pd[mi] = acc[mi][0]*d0.x + acc[mi][1]*d0.y + acc[mi][2]*d0.z + acc[mi][3]*d0.w
           + acc[mi][4]*d1.x + acc[mi][5]*d1.y + acc[mi][6]*d1.z + acc[mi][7]*d1.w;
  }
  #pragma unroll
  for (int o = 1; o < 16; o <<= 1){
    #pragma unroll
    for (int mi = 0; mi < 4; mi++){
      ps[mi] += __shfl_xor_sync(0xffffffffu, ps[mi], o);
      pd[mi] += __shfl_xor_sync(0xffffffffu, pd[mi], o);
    }
  }
  if (tx == 0){
    #pragma unroll
    for (int mi = 0; mi < 4; mi++){
      int row = i0 + 4*ty + mi;
      g_as[row*2 + h] = ps[mi];
      g_ad[row*2 + h] = pd[mi];
    }
  }
}

// ---------------- k_zero: init denom + acc (warp per row) ----------------
__global__ void k_zero(){
  int g = blockIdx.x*blockDim.x + threadIdx.x;
  int n = g >> 5, lane = g & 31;
  if (n >= NN) return;
  if (lane < 2) g_denom[n*2 + lane] = 0.f;
  float4 z = make_float4(0.f, 0.f, 0.f, 0.f);
  ((float4*)g_acc)[(size_t)n*64 + lane] = z;
  ((float4*)g_acc)[(size_t)n*64 + 32 + lane] = z;
}

// ---------------- k_filter (exact R10 winner): 512 thr, 16 warps ------------------
static constexpr int PITCH  = 272;
static constexpr int SM_A   = 0;
static constexpr int SM_B0  = 34816;
static constexpr int SM_B1  = 69632;
static constexpr int SM_SQ0 = 104448;
static constexpr int SM_SQ1 = 104960;
static constexpr int SM_TOT = 105472;

__global__ __launch_bounds__(512, 1) void k_filter(){
  extern __shared__ char smem[];
  uint32_t sbase = smem_u32(smem);
  int tid = threadIdx.x;
  int wid = tid >> 5, lane = tid & 31;
  int wr = wid & 7, wc = wid >> 3;
  int ib = blockIdx.x >> 1, split = blockIdx.x & 1;
  int i0 = ib*128;

  #pragma unroll
  for (int l = 0; l < 4; l++){
    int idx = tid + l*512;
    int r = idx >> 4, c = idx & 15;
    uint4 v = ((const uint4*)(g_xbf + (size_t)(i0 + r)*128))[c];
    *(uint4*)(smem + SM_A + r*PITCH + c*16) = v;
  }
  {
    int j0 = split*4096;
    #pragma unroll
    for (int l = 0; l < 4; l++){
      int idx = tid + l*512;
      int r = idx >> 4, c = idx & 15;
      uint4 v = ((const uint4*)(g_xbf + (size_t)(j0 + r)*128))[c];
      *(uint4*)(smem + SM_B0 + r*PITCH + c*16) = v;
    }
    if (tid < 128) ((float*)(smem + SM_SQ0))[tid] = g_sq[j0 + tid];
  }
  __syncthreads();

  uint32_t aAddr = sbase + SM_A
                 + (uint32_t)(16*wr + (lane & 7) + 8*((lane >> 3) & 1))*PITCH
                 + (uint32_t)(((lane >> 4) & 1) << 4);
  uint32_t bRowOff = (uint32_t)(64*wc + (lane & 7) + 8*((lane >> 4) & 1))*PITCH
                   + (uint32_t)(((lane >> 3) & 1) << 4);

  unsigned long long bu[4], bl[4];
  #pragma unroll
  for (int s = 0; s < 4; s++){ bu[s] = ~0ull; bl[s] = ~0ull; }
  float thrU = 1e30f, thrL = 1e30f;

  int q = lane & 3;
  int rsub = lane >> 2;

  for (int t = 0; t < 32; t++){
    int j0 = split*4096 + t*128;
    uint32_t bBase = sbase + ((t & 1) ? SM_B1 : SM_B0);
    const float* sq = (const float*)(smem + ((t & 1) ? SM_SQ1 : SM_SQ0));

    uint4 pf[4]; float sqv = 0.f;
    if (t < 31){
      int j0n = j0 + 128;
      #pragma unroll
      for (int l = 0; l < 4; l++){
        int idx = tid + l*512;
        int r = idx >> 4, c = idx & 15;
        pf[l] = ((const uint4*)(g_xbf + (size_t)(j0n + r)*128))[c];
      }
      if (tid < 128) sqv = g_sq[j0n + tid];
    }

    float acc[8][4];
    #pragma unroll
    for (int a = 0; a < 8; a++)
      #pragma unroll
      for (int b = 0; b < 4; b++) acc[a][b] = 0.f;

    #pragma unroll
    for (int ks = 0; ks < 8; ks++){
      uint32_t A[4];
      ldsm4(A[0], A[1], A[2], A[3], aAddr + ks*32);
      #pragma unroll
      for (int p = 0; p < 4; p++){
        uint32_t b0, b1, b2, b3;
        ldsm4(b0, b1, b2, b3, bBase + bRowOff + (uint32_t)(p*16)*PITCH + ks*32);
        mma16816(acc[2*p],   A, b0, b1);
        mma16816(acc[2*p+1], A, b2, b3);
      }
    }

    #pragma unroll
    for (int tt = 0; tt < 8; tt++){
      int c0 = 64*wc + 16*(tt >> 1) + 8*(tt & 1) + 2*q;
      float sq0 = sq[c0], sq1 = sq[c0 + 1];
      float du0 = fmaf(-2.0f, acc[tt][0], sq0);
      float du1 = fmaf(-2.0f, acc[tt][1], sq1);
      float dl0 = fmaf(-2.0f, acc[tt][2], sq0);
      float dl1 = fmaf(-2.0f, acc[tt][3], sq1);
      if (du0 < thrU){
        ins4(((unsigned long long)encf(du0) << 32) | (unsigned)(j0 + c0), bu);
        thrU = fminf(decf((unsigned)(bu[3] >> 32)), 1e30f);
      }
      if (du1 < thrU){
        ins4(((unsigned long long)encf(du1) << 32) | (unsigned)(j0 + c0 + 1), bu);
        thrU = fminf(decf((unsigned)(bu[3] >> 32)), 1e30f);
      }
      if (dl0 < thrL){
        ins4(((unsigned long long)encf(dl0) << 32) | (unsigned)(j0 + c0), bl);
        thrL = fminf(decf((unsigned)(bl[3] >> 32)), 1e30f);
      }
      if (dl1 < thrL){
        ins4(((unsigned long long)encf(dl1) << 32) | (unsigned)(j0 + c0 + 1), bl);
        thrL = fminf(decf((unsigned)(bl[3] >> 32)), 1e30f);
      }
    }

    if (t < 31){
      char* nb = smem + (((t + 1) & 1) ? SM_B1 : SM_B0);
      #pragma unroll
      for (int l = 0; l < 4; l++){
        int idx = tid + l*512;
        int r = idx >> 4, c = idx & 15;
        *(uint4*)(nb + r*PITCH + c*16) = pf[l];
      }
      if (tid < 128) ((float*)(smem + (((t + 1) & 1) ? SM_SQ1 : SM_SQ0)))[tid] = sqv;
    }
    __syncthreads();
  }

  int rowU = i0 + 16*wr + rsub;
  int rowL = rowU + 8;
  size_t baseU = ((size_t)split*NN + rowU)*32 + wc*16 + q*4;
  size_t baseL = ((size_t)split*NN + rowL)*32 + wc*16 + q*4;
  #pragma unroll
  for (int s = 0; s < 4; s++){
    g_cand[baseU + s] = bu[s];
    g_cand[baseL + s] = bl[s];
  }
}

// ---------------- k_rescore: exact fp32, warp per row, 64 candidates --------------
__global__ __launch_bounds__(256) void k_rescore(const float* __restrict__ X){
  int g = blockIdx.x*blockDim.x + threadIdx.x;
  int row = g >> 5, lane = g & 31;
  if (row >= NN) return;
  const float4* __restrict__ X4 = (const float4*)X;
  float4 xi = X4[(size_t)row*32 + lane];
  unsigned long long k0 = g_cand[(size_t)row*32 + lane];            // split 0
  unsigned long long k1 = g_cand[((size_t)NN + row)*32 + lane];     // split 1
  int jl0 = (int)(k0 & 0xffffffffull) & (NN - 1);
  int jl1 = (int)(k1 & 0xffffffffull) & (NN - 1);
  float sqi = g_sq[row];
  unsigned long long b0 = ~0ull, b1 = ~0ull, b2 = ~0ull;
  #pragma unroll 4
  for (int c = 0; c < 32; c++){
    int ja = __shfl_sync(0xffffffffu, jl0, c);
    int jb = __shfl_sync(0xffffffffu, jl1, c);
    float4 xa = X4[(size_t)ja*32 + lane];
    float4 xb = X4[(size_t)jb*32 + lane];
    float pa = xi.x*xa.x + xi.y*xa.y + xi.z*xa.z + xi.w*xa.w;
    float pb = xi.x*xb.x + xi.y*xb.y + xi.z*xb.z + xi.w*xb.w;
    #pragma unroll
    for (int o = 16; o; o >>= 1){
      pa += __shfl_xor_sync(0xffffffffu, pa, o);
      pb += __shfl_xor_sync(0xffffffffu, pb, o);
    }
    float d2a = (sqi + g_sq[ja]) - 2.0f*pa;
    float d2b = (sqi + g_sq[jb]) - 2.0f*pb;
    ins3(((unsigned long long)encf(d2a) << 32) | (unsigned)ja, b0, b1, b2);
    ins3(((unsigned long long)encf(d2b) << 32) | (unsigned)jb, b0, b1, b2);
  }
  if (lane == 0){
    g_nbr[row*3+0] = (int)(b0 & 0xffffffffull);
    g_nbr[row*3+1] = (int)(b1 & 0xffffffffull);
    g_nbr[row*3+2] = (int)(b2 & 0xffffffffull);
  }
}

// ---------------- k_edge: fused softmax-weight + aggregate (warp per edge-head) ----
__global__ void k_edge(){
  int g = blockIdx.x*blockDim.x + threadIdx.x;
  int eh = g >> 5, lane = g & 31;
  if (eh >= NE*2) return;
  int e = eh >> 1, h = eh & 1;
  int s = e/3;
  int d = g_nbr[e];
  float v = g_as[s*2+h] + g_ad[d*2+h];
  v = v > 0.f ? v : 0.2f*v;
  float w = __expf(v);
  if (lane == 0) atomicAdd(&g_denom[d*2+h], w);
  const float4* xp4 = (const float4*)g_xp;
  float4 xv = xp4[(size_t)s*64 + h*32 + lane];
  float* dst = &g_acc[(size_t)d*256 + h*128 + lane*4];
  atomicAdd(dst+0, w*xv.x);
  atomicAdd(dst+1, w*xv.y);
  atomicAdd(dst+2, w*xv.z);
  atomicAdd(dst+3, w*xv.w);
}

// ---------------- k_final: normalize + head-mean + bias + LN + ReLU + residual -----
__global__ void k_final(const float* __restrict__ X,
                        const float* __restrict__ bias,
                        const float* __restrict__ gamma,
                        const float* __restrict__ beta,
                        float* __restrict__ out){
  int g = blockIdx.x*blockDim.x + threadIdx.x;
  int n = g >> 5, lane = g & 31;
  if (n >= NN) return;
  float inv0 = 1.0f / g_denom[n*2+0];
  float inv1 = 1.0f / g_denom[n*2+1];
  float v[4];
  #pragma unroll
  for (int c = 0; c < 4; c++){
    int dd = lane*4 + c;
    float a0 = g_acc[(size_t)n*256 + dd] * inv0;
    float a1 = g_acc[(size_t)n*256 + 128 + dd] * inv1;
    v[c] = 0.5f*(a0 + a1) + bias[dd];
  }
  float s = v[0]+v[1]+v[2]+v[3];
  #pragma unroll
  for (int o = 16; o; o >>= 1) s += __shfl_xor_sync(0xffffffffu, s, o);
  float mu = s * (1.0f/128.0f);
  float q = 0.f;
  #pragma unroll
  for (int c = 0; c < 4; c++){ float t = v[c]-mu; q += t*t; }
  #pragma unroll
  for (int o = 16; o; o >>= 1) q += __shfl_xor_sync(0xffffffffu, q, o);
  float rstd = rsqrtf(q*(1.0f/128.0f) + 1e-5f);
  #pragma unroll
  for (int c = 0; c < 4; c++){
    int dd = lane*4 + c;
    float y = (v[c]-mu)*rstd*gamma[dd] + beta[dd];
    y = y > 0.f ? y : 0.f;
    out[(size_t)n*128 + dd] = X[(size_t)n*128 + dd] + y;
  }
}

// ---------------- launch ----------------
extern "C" void kernel_launch(void* const* d_in, const int* in_sizes, int n_in,
                              void* d_out, int out_size) {
  const float* prototypes = (const float*)d_in[0];
  // d_in[1] = labels (unused in forward)
  const float* W       = (const float*)d_in[2];
  const float* att_src = (const float*)d_in[3];
  const float* att_dst = (const float*)d_in[4];
  const float* bias    = (const float*)d_in[5];
  const float* gamma   = (const float*)d_in[6];
  const float* beta    = (const float*)d_in[7];
  float* out = (float*)d_out;

  cudaFuncSetAttribute(k_filter, cudaFuncAttributeMaxDynamicSharedMemorySize, SM_TOT);
  cudaFuncSetAttribute(k_xp, cudaFuncAttributeMaxDynamicSharedMemorySize, XP_SMEM);

  // order: k_filter stays at launch index 3 (the ncu-profiled slot)
  k_prep<<<NN/8, 256>>>((const float4*)prototypes);
  k_xp<<<256, 256, XP_SMEM>>>(prototypes, W, att_src, att_dst);
  k_zero<<<NN/8, 256>>>();
  k_filter<<<128, 512, SM_TOT>>>();
  k_rescore<<<NN/8, 256>>>(prototypes);
  k_edge<<<(NE*2*32+255)/256, 256>>>();
  k_final<<<NN/8, 256>>>(prototypes, bias, gamma, beta, out);
}